// round 3
// baseline (speedup 1.0000x reference)
#include <cuda_runtime.h>
#include <cuda_bf16.h>

// Batched 1D linear interpolation with clamped extrapolation.
// t: [B, N] sorted per row, v: [B, N], r: [B, M]  ->  out: [B, M]
//
// One CTA per row. Knots as interleaved (t,v) float2 pairs in SMEM.
// Per-row bucket table P[k] (ushort, KB uniform buckets over [tmin,tmax],
// sentinel P[KB]=NN) confines each query's searchsorted position to
// [P[k], P[k+1]] (expected width ~0.5 knots). Refinement is a warp-voted
// loop with a fully BRANCHLESS body (no divergence replays). Fast division
// via __fdividef (tolerance 1e-3; we are at ~4e-8).

#define NN 4096
#define MM 4096
#define KB 8063
#define TABLE (KB + 1)               // 8064 entries, P[KB] = NN sentinel
#define THREADS 512
#define QPT (MM / THREADS)           // 8 queries per thread

__device__ __forceinline__ int bucket_of(float x, float tmin, float scale) {
    // monotone nondecreasing in x
    int k = (int)((x - tmin) * scale);
    k = (k < 0) ? 0 : k;
    k = (k > KB - 1) ? KB - 1 : k;
    return k;
}

__global__ __launch_bounds__(THREADS, 3)
void interp1d_kernel(const float* __restrict__ t,
                     const float* __restrict__ v,
                     const float* __restrict__ r,
                     float* __restrict__ out) {
    __shared__ float2         tv[NN];     // 32768 B
    __shared__ unsigned short P[TABLE];   // 16128 B  (total 48896 <= 48KB+1K static limit)

    const int row = blockIdx.x;
    const float* trow = t + (size_t)row * NN;
    const float* vrow = v + (size_t)row * NN;
    const float* rrow = r + (size_t)row * MM;
    float*       orow = out + (size_t)row * MM;
    const int tid = threadIdx.x;

    // ---- Stage knot pairs (float4 LDG, STS.64) ----
    const float4* t4 = reinterpret_cast<const float4*>(trow);
    const float4* v4 = reinterpret_cast<const float4*>(vrow);
    #pragma unroll
    for (int i = 0; i < NN / 4 / THREADS; i++) {       // 2 iterations
        int i4 = tid + i * THREADS;
        float4 a = t4[i4];
        float4 b = v4[i4];
        int base = i4 * 4;
        tv[base + 0] = make_float2(a.x, b.x);
        tv[base + 1] = make_float2(a.y, b.y);
        tv[base + 2] = make_float2(a.z, b.z);
        tv[base + 3] = make_float2(a.w, b.w);
    }
    // ---- Init table to NN (covers the P[KB] sentinel too) ----
    #pragma unroll
    for (int i = 0; i < (TABLE + THREADS - 1) / THREADS; i++) {
        int j = tid + i * THREADS;
        if (j < TABLE) P[j] = (unsigned short)NN;
    }
    __syncthreads();

    const float tmin   = tv[0].x;
    const float tmax   = tv[NN - 1].x;
    const float vfirst = tv[0].y;
    const float vlast  = tv[NN - 1].y;
    const float span   = tmax - tmin;
    const float scale  = (span > 0.0f) ? (float)KB / span : 0.0f;

    // ---- Build: knot j owns table range (bucket(t[j-1]), bucket(t[j])] ----
    #pragma unroll
    for (int i = 0; i < NN / THREADS; i++) {           // 8 iterations
        int j = tid + i * THREADS;
        int bj = bucket_of(tv[j].x, tmin, scale);
        int bp = (j == 0) ? -1 : bucket_of(tv[j - 1].x, tmin, scale);
        for (int k = bp + 1; k <= bj; k++) P[k] = (unsigned short)j;
    }
    __syncthreads();

    // ---- Queries: 8 per thread, 4 register-interleaved at a time ----
    #pragma unroll
    for (int b = 0; b < QPT / 4; b++) {
        float rv[4];
        #pragma unroll
        for (int q = 0; q < 4; q++)
            rv[q] = rrow[tid + (b * 4 + q) * THREADS];  // coalesced

        int lo[4], hi[4];
        #pragma unroll
        for (int q = 0; q < 4; q++) {
            int k = bucket_of(rv[q], tmin, scale);
            lo[q] = P[k];
            hi[q] = P[k + 1];                            // sentinel makes this safe
        }

        // warp-voted refinement with branchless body: pos = count(t <= r)
        while (__any_sync(0xffffffffu,
                          (lo[0] < hi[0]) | (lo[1] < hi[1]) |
                          (lo[2] < hi[2]) | (lo[3] < hi[3]))) {
            #pragma unroll
            for (int q = 0; q < 4; q++) {
                int mid  = (lo[q] + hi[q]) >> 1;
                int midc = (mid < NN - 1) ? mid : NN - 1;  // OOB guard for dead lanes
                float tm = tv[midc].x;
                bool go  = lo[q] < hi[q];
                bool le  = tm <= rv[q];
                lo[q] = (go &&  le) ? mid + 1 : lo[q];
                hi[q] = (go && !le) ? mid     : hi[q];
            }
        }

        float res[4];
        #pragma unroll
        for (int q = 0; q < 4; q++) {
            int idx = lo[q];
            idx = (idx < 1) ? 1 : idx;
            idx = (idx > NN - 1) ? NN - 1 : idx;
            float2 p0 = tv[idx - 1];
            float2 p1 = tv[idx];
            float d = p1.x - p0.x;
            float denom = (d == 0.0f) ? 1.0f : d;
            float o = p0.y + (rv[q] - p0.x) * __fdividef(p1.y - p0.y, denom);
            o = (rv[q] < tmin) ? vfirst : o;   // clamped extrapolation
            o = (rv[q] > tmax) ? vlast  : o;
            res[q] = o;
        }

        #pragma unroll
        for (int q = 0; q < 4; q++)
            orow[tid + (b * 4 + q) * THREADS] = res[q];
    }
}

extern "C" void kernel_launch(void* const* d_in, const int* in_sizes, int n_in,
                              void* d_out, int out_size) {
    const float* t = (const float*)d_in[0];
    const float* v = (const float*)d_in[1];
    const float* r = (const float*)d_in[2];
    float* out = (float*)d_out;

    int B = in_sizes[0] / NN;   // 2048 for the reference shape
    interp1d_kernel<<<B, THREADS>>>(t, v, r, out);
}